// round 6
// baseline (speedup 1.0000x reference)
#include <cuda_runtime.h>
#include <cuda_bf16.h>
#include <math.h>

// Problem constants (fixed by dataset): N=100000, E=1600000, dims 128->64->32
#define IN_F  128
#define HID_F 64
#define OUT_F 32
#define N_MAX 100000
#define E_MAX 1600000
#define NB_MAX 512         // ceil(N/256) = 391 < 512

// ---- device scratch (no cudaMalloc allowed) ----
__device__ int   g_deg    [N_MAX];       // 1 + in-degree
__device__ float g_dinv   [N_MAX];
__device__ int   g_rowstart[N_MAX];      // CSR offsets (in-degree only)
__device__ int   g_cursor [N_MAX];       // fill cursors
__device__ int   g_bsum   [NB_MAX];      // per-block indegree sums
__device__ int   g_bofs   [NB_MAX];      // exclusive scan of block sums
__device__ int   g_csr_src[E_MAX];
__device__ float g_csr_w  [E_MAX];
__device__ float g_H1  [(size_t)N_MAX * HID_F];   // x @ W1
__device__ float g_agg1[(size_t)N_MAX * HID_F];   // relu(aggregated layer-1)
__device__ float g_H2  [(size_t)N_MAX * OUT_F];   // relu_agg1 @ W2

// ---------------------------------------------------------------------------
// K0: deg init to 1 (self loop)
__global__ void k_deg_init(int N) {
    int n = blockIdx.x * blockDim.x + threadIdx.x;
    if (n < N) g_deg[n] = 1;
}

// K1: histogram in-degree (edge_index is int32 — JAX x64 disabled)
__global__ void k_edge_prep(const int* __restrict__ ei, int E) {
    int e = blockIdx.x * blockDim.x + threadIdx.x;
    if (e < E) {
        int d = ei[E + e];
        atomicAdd(&g_deg[d], 1);
    }
}

// ---------------------------------------------------------------------------
// SA: per-block indegree sums + dinv (fused: deg final after edge_prep)
__global__ __launch_bounds__(256) void k_scan_a(int N) {
    __shared__ int sh[256];
    int t = threadIdx.x;
    int n = blockIdx.x * 256 + t;
    int deg = (n < N) ? g_deg[n] : 1;
    if (n < N) g_dinv[n] = rsqrtf((float)deg);
    sh[t] = (n < N) ? (deg - 1) : 0;
    __syncthreads();
    for (int off = 128; off > 0; off >>= 1) {
        if (t < off) sh[t] += sh[t + off];
        __syncthreads();
    }
    if (t == 0) g_bsum[blockIdx.x] = sh[0];
}

// SB: exclusive scan of block sums — parallel Hillis-Steele (NB <= 512)
__global__ __launch_bounds__(512) void k_scan_b(int NB) {
    __shared__ int sh[512];
    int t = threadIdx.x;
    int v = (t < NB) ? g_bsum[t] : 0;
    sh[t] = v;
    __syncthreads();
    for (int off = 1; off < 512; off <<= 1) {
        int add = (t >= off) ? sh[t - off] : 0;
        __syncthreads();
        sh[t] += add;
        __syncthreads();
    }
    if (t < NB) g_bofs[t] = sh[t] - v;   // exclusive
}

// SC: in-block exclusive scan + block offset -> row_start, cursor
__global__ __launch_bounds__(256) void k_scan_c(int N) {
    __shared__ int sh[256];
    int t = threadIdx.x;
    int n = blockIdx.x * 256 + t;
    int v = (n < N) ? (g_deg[n] - 1) : 0;
    sh[t] = v;
    __syncthreads();
    for (int off = 1; off < 256; off <<= 1) {
        int add = (t >= off) ? sh[t - off] : 0;
        __syncthreads();
        sh[t] += add;
        __syncthreads();
    }
    if (n < N) {
        int excl = sh[t] - v + g_bofs[blockIdx.x];
        g_rowstart[n] = excl;
        g_cursor[n]   = excl;
    }
}

// Fill CSR: slot per edge via int atomic cursor; fold normalization coefficient
__global__ void k_fill(const int* __restrict__ ei, int E) {
    int e = blockIdx.x * blockDim.x + threadIdx.x;
    if (e < E) {
        int s = ei[e];
        int d = ei[E + e];
        int pos = atomicAdd(&g_cursor[d], 1);
        g_csr_src[pos] = s;
        g_csr_w[pos]   = g_dinv[s] * g_dinv[d];
    }
}

// ---------------------------------------------------------------------------
// GEMM1: H1[N,64] = x[N,128] @ W1[128,64]; 32-row tiles, W1 + x tile in SMEM
__global__ __launch_bounds__(256) void k_gemm1(const float* __restrict__ x,
                                               const float* __restrict__ W,
                                               int N) {
    __shared__ float Ws[IN_F * HID_F];   // 32 KB
    __shared__ float xs[32 * IN_F];      // 16 KB
    int t = threadIdx.x;
    for (int i = t; i < IN_F * HID_F; i += 256) Ws[i] = W[i];

    int row0 = blockIdx.x * 32;
    int rows = N - row0; if (rows > 32) rows = 32;

    const float4* xg  = (const float4*)(x + (size_t)row0 * IN_F);
    float4*       xs4 = (float4*)xs;
    const int NV = 32 * IN_F / 4;  // 1024
    for (int i = t; i < NV; i += 256) {
        int r = i / (IN_F / 4);
        xs4[i] = (r < rows) ? xg[i] : make_float4(0.f, 0.f, 0.f, 0.f);
    }
    __syncthreads();

    int r = t >> 3;            // 0..31
    int g = (t & 7) * 8;       // col group: 0,8,...,56
    if (r < rows) {
        float acc[8];
        #pragma unroll
        for (int i = 0; i < 8; ++i) acc[i] = 0.f;
        #pragma unroll 16
        for (int k = 0; k < IN_F; ++k) {
            float xv = xs[r * IN_F + k];
            float4 w0 = *(const float4*)&Ws[k * HID_F + g];
            float4 w1 = *(const float4*)&Ws[k * HID_F + g + 4];
            acc[0] = fmaf(xv, w0.x, acc[0]);
            acc[1] = fmaf(xv, w0.y, acc[1]);
            acc[2] = fmaf(xv, w0.z, acc[2]);
            acc[3] = fmaf(xv, w0.w, acc[3]);
            acc[4] = fmaf(xv, w1.x, acc[4]);
            acc[5] = fmaf(xv, w1.y, acc[5]);
            acc[6] = fmaf(xv, w1.z, acc[6]);
            acc[7] = fmaf(xv, w1.w, acc[7]);
        }
        float* out = g_H1 + (size_t)(row0 + r) * HID_F + g;
        *(float4*)(out)     = make_float4(acc[0], acc[1], acc[2], acc[3]);
        *(float4*)(out + 4) = make_float4(acc[4], acc[5], acc[6], acc[7]);
    }
}

// GEMM2: H2[N,32] = agg1[N,64] @ W2[64,32]  (agg1 already relu'd)
__global__ __launch_bounds__(256) void k_gemm2(const float* __restrict__ W, int N) {
    __shared__ float Ws[HID_F * OUT_F];  // 8 KB
    __shared__ float xs[32 * HID_F];     // 8 KB
    int t = threadIdx.x;
    for (int i = t; i < HID_F * OUT_F; i += 256) Ws[i] = W[i];

    int row0 = blockIdx.x * 32;
    int rows = N - row0; if (rows > 32) rows = 32;

    const float4* xg  = (const float4*)(g_agg1 + (size_t)row0 * HID_F);
    float4*       xs4 = (float4*)xs;
    const int NV = 32 * HID_F / 4;  // 512
    for (int i = t; i < NV; i += 256) {
        int r = i / (HID_F / 4);
        xs4[i] = (r < rows) ? xg[i] : make_float4(0.f, 0.f, 0.f, 0.f);
    }
    __syncthreads();

    int r = t >> 3;          // 0..31
    int g = (t & 7) * 4;     // col group: 0,4,...,28
    if (r < rows) {
        float acc[4] = {0.f, 0.f, 0.f, 0.f};
        #pragma unroll 16
        for (int k = 0; k < HID_F; ++k) {
            float xv = xs[r * HID_F + k];
            float4 w = *(const float4*)&Ws[k * OUT_F + g];
            acc[0] = fmaf(xv, w.x, acc[0]);
            acc[1] = fmaf(xv, w.y, acc[1]);
            acc[2] = fmaf(xv, w.z, acc[2]);
            acc[3] = fmaf(xv, w.w, acc[3]);
        }
        float* out = g_H2 + (size_t)(row0 + r) * OUT_F + g;
        *(float4*)out = make_float4(acc[0], acc[1], acc[2], acc[3]);
    }
}

// ---------------------------------------------------------------------------
// Gather1: one warp per node. Shuffle-batched: lanes cooperatively load 32
// (src,w) pairs coalesced, broadcast via shfl; H1 gathers become independent
// LDG.64s (high MLP). ReLU fused into store.
__global__ __launch_bounds__(256) void k_gather1(const float* __restrict__ b1, int N) {
    int n    = (blockIdx.x * blockDim.x + threadIdx.x) >> 5;
    int lane = threadIdx.x & 31;
    if (n >= N) return;

    float dn = g_dinv[n];
    float c  = dn * dn;
    float2 h  = *(const float2*)&g_H1[(size_t)n * HID_F + lane * 2];
    float2 bb = *(const float2*)&b1[lane * 2];
    float2 acc;
    acc.x = fmaf(h.x, c, bb.x);
    acc.y = fmaf(h.y, c, bb.y);

    int start = g_rowstart[n];
    int end   = start + g_deg[n] - 1;
    for (int base = start; base < end; base += 32) {
        int j = base + lane;
        int   sl = 0; float wl = 0.f;
        if (j < end) { sl = g_csr_src[j]; wl = g_csr_w[j]; }
        int cnt = end - base; if (cnt > 32) cnt = 32;
        #pragma unroll 4
        for (int k = 0; k < cnt; ++k) {
            int   sk = __shfl_sync(0xffffffffu, sl, k);
            float wk = __shfl_sync(0xffffffffu, wl, k);
            float2 v = *(const float2*)&g_H1[(size_t)sk * HID_F + lane * 2];
            acc.x = fmaf(wk, v.x, acc.x);
            acc.y = fmaf(wk, v.y, acc.y);
        }
    }
    float2 o;
    o.x = fmaxf(acc.x, 0.f);
    o.y = fmaxf(acc.y, 0.f);
    *(float2*)&g_agg1[(size_t)n * HID_F + lane * 2] = o;
}

// Gather2: one warp per node, 1 feature per lane, writes d_out.
__global__ __launch_bounds__(256) void k_gather2(const float* __restrict__ b2,
                                                 float* __restrict__ out, int N) {
    int n    = (blockIdx.x * blockDim.x + threadIdx.x) >> 5;
    int lane = threadIdx.x & 31;
    if (n >= N) return;

    float dn = g_dinv[n];
    float c  = dn * dn;
    float acc = fmaf(g_H2[(size_t)n * OUT_F + lane], c, b2[lane]);

    int start = g_rowstart[n];
    int end   = start + g_deg[n] - 1;
    for (int base = start; base < end; base += 32) {
        int j = base + lane;
        int   sl = 0; float wl = 0.f;
        if (j < end) { sl = g_csr_src[j]; wl = g_csr_w[j]; }
        int cnt = end - base; if (cnt > 32) cnt = 32;
        #pragma unroll 4
        for (int k = 0; k < cnt; ++k) {
            int   sk = __shfl_sync(0xffffffffu, sl, k);
            float wk = __shfl_sync(0xffffffffu, wl, k);
            acc = fmaf(wk, g_H2[(size_t)sk * OUT_F + lane], acc);
        }
    }
    out[(size_t)n * OUT_F + lane] = acc;
}

// ---------------------------------------------------------------------------
extern "C" void kernel_launch(void* const* d_in, const int* in_sizes, int n_in,
                              void* d_out, int out_size) {
    const float* x  = (const float*)d_in[0];
    const int*   ei = (const int*)d_in[1];      // int32 (JAX x64 disabled)
    const float* W1 = (const float*)d_in[2];
    const float* b1 = (const float*)d_in[3];
    const float* W2 = (const float*)d_in[4];
    const float* b2 = (const float*)d_in[5];
    float*       out = (float*)d_out;

    const int N = in_sizes[0] / IN_F;     // 100000
    const int E = in_sizes[1] / 2;        // 1600000
    const int NB = (N + 255) / 256;       // scan blocks

    const int T = 256;
    // degree + dinv + CSR build (int atomics only)
    k_deg_init <<<(N + T - 1) / T, T>>>(N);
    k_edge_prep<<<(E + T - 1) / T, T>>>(ei, E);
    k_scan_a<<<NB, 256>>>(N);                       // also computes dinv
    k_scan_b<<<1, 512>>>(NB);
    k_scan_c<<<NB, 256>>>(N);
    k_fill  <<<(E + T - 1) / T, T>>>(ei, E);

    // layer 1: GEMM -> gather (relu fused)
    k_gemm1  <<<(N + 31) / 32, 256>>>(x, W1, N);
    k_gather1<<<(N * 32 + T - 1) / T, T>>>(b1, N);

    // layer 2: GEMM -> gather (writes d_out)
    k_gemm2  <<<(N + 31) / 32, 256>>>(W2, N);
    k_gather2<<<(N * 32 + T - 1) / T, T>>>(b2, out, N);
}

// round 7
// speedup vs baseline: 1.7522x; 1.7522x over previous
#include <cuda_runtime.h>
#include <cuda_bf16.h>
#include <math.h>

// Problem constants (fixed by dataset): N=100000, E=1600000, dims 128->64->32
#define IN_F  128
#define HID_F 64
#define OUT_F 32
#define N_MAX 100000
#define E_MAX 1600000
#define NB_MAX 512         // ceil(N/256) = 391 < 512

// ---- device scratch (no cudaMalloc allowed) ----
__device__ int   g_deg    [N_MAX];       // 1 + in-degree
__device__ float g_dinv   [N_MAX];
__device__ int   g_rowstart[N_MAX];      // CSR offsets (in-degree only)
__device__ int   g_cursor [N_MAX];       // fill cursors
__device__ int   g_bsum   [NB_MAX];      // per-block indegree sums
__device__ int   g_bofs   [NB_MAX];      // exclusive scan of block sums
__device__ int2  g_csr    [E_MAX];       // packed (src, w-as-int)
__device__ float g_H1  [(size_t)N_MAX * HID_F];   // x @ W1
__device__ float g_agg1[(size_t)N_MAX * HID_F];   // relu(aggregated layer-1)
__device__ float g_H2  [(size_t)N_MAX * OUT_F];   // relu_agg1 @ W2

// ---------------------------------------------------------------------------
// K0: deg init to 1 (self loop)
__global__ void k_deg_init(int N) {
    int n = blockIdx.x * blockDim.x + threadIdx.x;
    if (n < N) g_deg[n] = 1;
}

// K1: histogram in-degree (edge_index is int32 — JAX x64 disabled)
__global__ void k_edge_prep(const int* __restrict__ ei, int E) {
    int e = blockIdx.x * blockDim.x + threadIdx.x;
    if (e < E) {
        int d = ei[E + e];
        atomicAdd(&g_deg[d], 1);
    }
}

// ---------------------------------------------------------------------------
// SA: per-block indegree sums + dinv (deg final after edge_prep)
__global__ __launch_bounds__(256) void k_scan_a(int N) {
    __shared__ int sh[256];
    int t = threadIdx.x;
    int n = blockIdx.x * 256 + t;
    int deg = (n < N) ? g_deg[n] : 1;
    if (n < N) g_dinv[n] = rsqrtf((float)deg);
    sh[t] = (n < N) ? (deg - 1) : 0;
    __syncthreads();
    for (int off = 128; off > 0; off >>= 1) {
        if (t < off) sh[t] += sh[t + off];
        __syncthreads();
    }
    if (t == 0) g_bsum[blockIdx.x] = sh[0];
}

// SB: exclusive scan of block sums — parallel Hillis-Steele (NB <= 512)
__global__ __launch_bounds__(512) void k_scan_b(int NB) {
    __shared__ int sh[512];
    int t = threadIdx.x;
    int v = (t < NB) ? g_bsum[t] : 0;
    sh[t] = v;
    __syncthreads();
    for (int off = 1; off < 512; off <<= 1) {
        int add = (t >= off) ? sh[t - off] : 0;
        __syncthreads();
        sh[t] += add;
        __syncthreads();
    }
    if (t < NB) g_bofs[t] = sh[t] - v;   // exclusive
}

// SC: in-block exclusive scan + block offset -> row_start, cursor
__global__ __launch_bounds__(256) void k_scan_c(int N) {
    __shared__ int sh[256];
    int t = threadIdx.x;
    int n = blockIdx.x * 256 + t;
    int v = (n < N) ? (g_deg[n] - 1) : 0;
    sh[t] = v;
    __syncthreads();
    for (int off = 1; off < 256; off <<= 1) {
        int add = (t >= off) ? sh[t - off] : 0;
        __syncthreads();
        sh[t] += add;
        __syncthreads();
    }
    if (n < N) {
        int excl = sh[t] - v + g_bofs[blockIdx.x];
        g_rowstart[n] = excl;
        g_cursor[n]   = excl;
    }
}

// Fill CSR: one packed 8B store per edge (was 2 random 4B stores)
__global__ void k_fill(const int* __restrict__ ei, int E) {
    int e = blockIdx.x * blockDim.x + threadIdx.x;
    if (e < E) {
        int s = ei[e];
        int d = ei[E + e];
        int pos = atomicAdd(&g_cursor[d], 1);
        g_csr[pos] = make_int2(s, __float_as_int(g_dinv[s] * g_dinv[d]));
    }
}

// ---------------------------------------------------------------------------
// GEMM1: H1[N,64] = x[N,128] @ W1[128,64]
// 128-row x 64-col block, 256 threads, 8x4 micro-tile per thread.
// x chunk stored k-major (transposed, stride-padded) so compute loads are
// half-warp broadcasts; 32 FMA per 3 LDS.128 -> FMA-issue-bound.
#define KC 32
#define XT_STRIDE 132   // 128 + 4: float4-aligned, breaks bank-conflict stride
__global__ __launch_bounds__(256) void k_gemm1(const float* __restrict__ x,
                                               const float* __restrict__ W,
                                               int N) {
    __shared__ float Ws[IN_F * HID_F];      // 32 KB, [k][64]
    __shared__ float xsT[KC * XT_STRIDE];   // ~16.5 KB, [k][row]
    int t  = threadIdx.x;
    int ty = t >> 4;        // 0..15 -> rows ty*8 .. ty*8+7
    int tx = t & 15;        // 0..15 -> cols tx*4 .. tx*4+3
    int row0 = blockIdx.x * 128;

    for (int i = t; i < IN_F * HID_F / 4; i += 256)
        ((float4*)Ws)[i] = ((const float4*)W)[i];

    float acc[8][4];
    #pragma unroll
    for (int i = 0; i < 8; ++i) {
        #pragma unroll
        for (int j = 0; j < 4; ++j) acc[i][j] = 0.f;
    }

    for (int kc = 0; kc < IN_F; kc += KC) {
        __syncthreads();
        // load + transpose x chunk: 128 rows x KC k-values (1024 float4)
        for (int i = t; i < 128 * (KC / 4); i += 256) {
            int r  = i >> 3;       // row within tile
            int kq = i & 7;        // float4 index within chunk
            int row = row0 + r;
            float4 v = make_float4(0.f, 0.f, 0.f, 0.f);
            if (row < N) v = *(const float4*)&x[(size_t)row * IN_F + kc + kq * 4];
            xsT[(kq * 4 + 0) * XT_STRIDE + r] = v.x;
            xsT[(kq * 4 + 1) * XT_STRIDE + r] = v.y;
            xsT[(kq * 4 + 2) * XT_STRIDE + r] = v.z;
            xsT[(kq * 4 + 3) * XT_STRIDE + r] = v.w;
        }
        __syncthreads();
        #pragma unroll
        for (int k = 0; k < KC; ++k) {
            float4 xa = *(const float4*)&xsT[k * XT_STRIDE + ty * 8];
            float4 xb = *(const float4*)&xsT[k * XT_STRIDE + ty * 8 + 4];
            float4 w  = *(const float4*)&Ws[(kc + k) * HID_F + tx * 4];
            acc[0][0] = fmaf(xa.x, w.x, acc[0][0]);
            acc[0][1] = fmaf(xa.x, w.y, acc[0][1]);
            acc[0][2] = fmaf(xa.x, w.z, acc[0][2]);
            acc[0][3] = fmaf(xa.x, w.w, acc[0][3]);
            acc[1][0] = fmaf(xa.y, w.x, acc[1][0]);
            acc[1][1] = fmaf(xa.y, w.y, acc[1][1]);
            acc[1][2] = fmaf(xa.y, w.z, acc[1][2]);
            acc[1][3] = fmaf(xa.y, w.w, acc[1][3]);
            acc[2][0] = fmaf(xa.z, w.x, acc[2][0]);
            acc[2][1] = fmaf(xa.z, w.y, acc[2][1]);
            acc[2][2] = fmaf(xa.z, w.z, acc[2][2]);
            acc[2][3] = fmaf(xa.z, w.w, acc[2][3]);
            acc[3][0] = fmaf(xa.w, w.x, acc[3][0]);
            acc[3][1] = fmaf(xa.w, w.y, acc[3][1]);
            acc[3][2] = fmaf(xa.w, w.z, acc[3][2]);
            acc[3][3] = fmaf(xa.w, w.w, acc[3][3]);
            acc[4][0] = fmaf(xb.x, w.x, acc[4][0]);
            acc[4][1] = fmaf(xb.x, w.y, acc[4][1]);
            acc[4][2] = fmaf(xb.x, w.z, acc[4][2]);
            acc[4][3] = fmaf(xb.x, w.w, acc[4][3]);
            acc[5][0] = fmaf(xb.y, w.x, acc[5][0]);
            acc[5][1] = fmaf(xb.y, w.y, acc[5][1]);
            acc[5][2] = fmaf(xb.y, w.z, acc[5][2]);
            acc[5][3] = fmaf(xb.y, w.w, acc[5][3]);
            acc[6][0] = fmaf(xb.z, w.x, acc[6][0]);
            acc[6][1] = fmaf(xb.z, w.y, acc[6][1]);
            acc[6][2] = fmaf(xb.z, w.z, acc[6][2]);
            acc[6][3] = fmaf(xb.z, w.w, acc[6][3]);
            acc[7][0] = fmaf(xb.w, w.x, acc[7][0]);
            acc[7][1] = fmaf(xb.w, w.y, acc[7][1]);
            acc[7][2] = fmaf(xb.w, w.z, acc[7][2]);
            acc[7][3] = fmaf(xb.w, w.w, acc[7][3]);
        }
    }
    #pragma unroll
    for (int i = 0; i < 8; ++i) {
        int row = row0 + ty * 8 + i;
        if (row < N)
            *(float4*)&g_H1[(size_t)row * HID_F + tx * 4] =
                make_float4(acc[i][0], acc[i][1], acc[i][2], acc[i][3]);
    }
}

// GEMM2: H2[N,32] = agg1[N,64] @ W2[64,32]  (agg1 already relu'd)
__global__ __launch_bounds__(256) void k_gemm2(const float* __restrict__ W, int N) {
    __shared__ float Ws[HID_F * OUT_F];  // 8 KB
    __shared__ float xs[32 * HID_F];     // 8 KB
    int t = threadIdx.x;
    for (int i = t; i < HID_F * OUT_F; i += 256) Ws[i] = W[i];

    int row0 = blockIdx.x * 32;
    int rows = N - row0; if (rows > 32) rows = 32;

    const float4* xg  = (const float4*)(g_agg1 + (size_t)row0 * HID_F);
    float4*       xs4 = (float4*)xs;
    const int NV = 32 * HID_F / 4;  // 512
    for (int i = t; i < NV; i += 256) {
        int r = i / (HID_F / 4);
        xs4[i] = (r < rows) ? xg[i] : make_float4(0.f, 0.f, 0.f, 0.f);
    }
    __syncthreads();

    int r = t >> 3;          // 0..31
    int g = (t & 7) * 4;     // col group: 0,4,...,28
    if (r < rows) {
        float acc[4] = {0.f, 0.f, 0.f, 0.f};
        #pragma unroll 16
        for (int k = 0; k < HID_F; ++k) {
            float xv = xs[r * HID_F + k];
            float4 w = *(const float4*)&Ws[k * OUT_F + g];
            acc[0] = fmaf(xv, w.x, acc[0]);
            acc[1] = fmaf(xv, w.y, acc[1]);
            acc[2] = fmaf(xv, w.z, acc[2]);
            acc[3] = fmaf(xv, w.w, acc[3]);
        }
        float* out = g_H2 + (size_t)(row0 + r) * OUT_F + g;
        *(float4*)out = make_float4(acc[0], acc[1], acc[2], acc[3]);
    }
}

// ---------------------------------------------------------------------------
// Gather1: one warp per node, shuffle-batched CSR (packed int2). ReLU fused.
__global__ __launch_bounds__(256) void k_gather1(const float* __restrict__ b1, int N) {
    int n    = (blockIdx.x * blockDim.x + threadIdx.x) >> 5;
    int lane = threadIdx.x & 31;
    if (n >= N) return;

    float dn = g_dinv[n];
    float c  = dn * dn;
    float2 h  = *(const float2*)&g_H1[(size_t)n * HID_F + lane * 2];
    float2 bb = *(const float2*)&b1[lane * 2];
    float2 acc;
    acc.x = fmaf(h.x, c, bb.x);
    acc.y = fmaf(h.y, c, bb.y);

    int start = g_rowstart[n];
    int end   = start + g_deg[n] - 1;
    for (int base = start; base < end; base += 32) {
        int j = base + lane;
        int   sl = 0; float wl = 0.f;
        if (j < end) { int2 p = g_csr[j]; sl = p.x; wl = __int_as_float(p.y); }
        int cnt = end - base; if (cnt > 32) cnt = 32;
        #pragma unroll 4
        for (int k = 0; k < cnt; ++k) {
            int   sk = __shfl_sync(0xffffffffu, sl, k);
            float wk = __shfl_sync(0xffffffffu, wl, k);
            float2 v = *(const float2*)&g_H1[(size_t)sk * HID_F + lane * 2];
            acc.x = fmaf(wk, v.x, acc.x);
            acc.y = fmaf(wk, v.y, acc.y);
        }
    }
    float2 o;
    o.x = fmaxf(acc.x, 0.f);
    o.y = fmaxf(acc.y, 0.f);
    *(float2*)&g_agg1[(size_t)n * HID_F + lane * 2] = o;
}

// Gather2: one warp per node, 1 feature per lane, writes d_out.
__global__ __launch_bounds__(256) void k_gather2(const float* __restrict__ b2,
                                                 float* __restrict__ out, int N) {
    int n    = (blockIdx.x * blockDim.x + threadIdx.x) >> 5;
    int lane = threadIdx.x & 31;
    if (n >= N) return;

    float dn = g_dinv[n];
    float c  = dn * dn;
    float acc = fmaf(g_H2[(size_t)n * OUT_F + lane], c, b2[lane]);

    int start = g_rowstart[n];
    int end   = start + g_deg[n] - 1;
    for (int base = start; base < end; base += 32) {
        int j = base + lane;
        int   sl = 0; float wl = 0.f;
        if (j < end) { int2 p = g_csr[j]; sl = p.x; wl = __int_as_float(p.y); }
        int cnt = end - base; if (cnt > 32) cnt = 32;
        #pragma unroll 4
        for (int k = 0; k < cnt; ++k) {
            int   sk = __shfl_sync(0xffffffffu, sl, k);
            float wk = __shfl_sync(0xffffffffu, wl, k);
            acc = fmaf(wk, g_H2[(size_t)sk * OUT_F + lane], acc);
        }
    }
    out[(size_t)n * OUT_F + lane] = acc;
}

// ---------------------------------------------------------------------------
extern "C" void kernel_launch(void* const* d_in, const int* in_sizes, int n_in,
                              void* d_out, int out_size) {
    const float* x  = (const float*)d_in[0];
    const int*   ei = (const int*)d_in[1];      // int32 (JAX x64 disabled)
    const float* W1 = (const float*)d_in[2];
    const float* b1 = (const float*)d_in[3];
    const float* W2 = (const float*)d_in[4];
    const float* b2 = (const float*)d_in[5];
    float*       out = (float*)d_out;

    const int N = in_sizes[0] / IN_F;     // 100000
    const int E = in_sizes[1] / 2;        // 1600000
    const int NB = (N + 255) / 256;       // scan blocks

    const int T = 256;
    // degree + dinv + CSR build (int atomics only)
    k_deg_init <<<(N + T - 1) / T, T>>>(N);
    k_edge_prep<<<(E + T - 1) / T, T>>>(ei, E);
    k_scan_a<<<NB, 256>>>(N);                       // also computes dinv
    k_scan_b<<<1, 512>>>(NB);
    k_scan_c<<<NB, 256>>>(N);
    k_fill  <<<(E + T - 1) / T, T>>>(ei, E);

    // layer 1: GEMM -> gather (relu fused)
    k_gemm1  <<<(N + 127) / 128, 256>>>(x, W1, N);
    k_gather1<<<(N * 32 + T - 1) / T, T>>>(b1, N);

    // layer 2: GEMM -> gather (writes d_out)
    k_gemm2  <<<(N + 31) / 32, 256>>>(W2, N);
    k_gather2<<<(N * 32 + T - 1) / T, T>>>(b2, out, N);
}

// round 8
// speedup vs baseline: 1.7910x; 1.0222x over previous
#include <cuda_runtime.h>
#include <cuda_bf16.h>
#include <math.h>

// Problem constants (fixed by dataset): N=100000, E=1600000, dims 128->64->32
#define IN_F  128
#define HID_F 64
#define OUT_F 32
#define N_MAX 100000
#define E_MAX 1600000
#define NB_MAX 512         // ceil(N/256) = 391 < 512

typedef unsigned long long u64;

// ---- packed f32x2 helpers (sm_103a FFMA2 — only reachable via PTX) ----
__device__ __forceinline__ u64 pack2(float lo, float hi) {
    u64 r; asm("mov.b64 %0, {%1, %2};" : "=l"(r) : "f"(lo), "f"(hi)); return r;
}
__device__ __forceinline__ void fma2(u64& d, u64 a, u64 b) {
    asm("fma.rn.f32x2 %0, %1, %2, %0;" : "+l"(d) : "l"(a), "l"(b));
}
__device__ __forceinline__ float2 unpack2(u64 v) {
    float2 f; asm("mov.b64 {%0, %1}, %2;" : "=f"(f.x), "=f"(f.y) : "l"(v)); return f;
}

// ---- device scratch (no cudaMalloc allowed) ----
__device__ int   g_deg    [N_MAX];       // 1 + in-degree
__device__ float g_dinv   [N_MAX];
__device__ int   g_rowstart[N_MAX];      // CSR offsets (in-degree only)
__device__ int   g_cursor [N_MAX];       // fill cursors
__device__ int   g_bsum   [NB_MAX];      // per-block indegree sums
__device__ int   g_bofs   [NB_MAX];      // exclusive scan of block sums
__device__ int2  g_csr    [E_MAX];       // packed (src, w-as-int)
__device__ float g_H1  [(size_t)N_MAX * HID_F];   // x @ W1
__device__ float g_agg1[(size_t)N_MAX * HID_F];   // relu(aggregated layer-1)
__device__ float g_H2  [(size_t)N_MAX * OUT_F];   // relu_agg1 @ W2

// ---------------------------------------------------------------------------
// K0: deg init to 1 (self loop)
__global__ void k_deg_init(int N) {
    int n = blockIdx.x * blockDim.x + threadIdx.x;
    if (n < N) g_deg[n] = 1;
}

// K1: histogram in-degree (edge_index is int32 — JAX x64 disabled)
__global__ void k_edge_prep(const int* __restrict__ ei, int E) {
    int e = blockIdx.x * blockDim.x + threadIdx.x;
    if (e < E) {
        int d = ei[E + e];
        atomicAdd(&g_deg[d], 1);
    }
}

// ---------------------------------------------------------------------------
// SA: per-block indegree sums + dinv (deg final after edge_prep)
__global__ __launch_bounds__(256) void k_scan_a(int N) {
    __shared__ int sh[256];
    int t = threadIdx.x;
    int n = blockIdx.x * 256 + t;
    int deg = (n < N) ? g_deg[n] : 1;
    if (n < N) g_dinv[n] = rsqrtf((float)deg);
    sh[t] = (n < N) ? (deg - 1) : 0;
    __syncthreads();
    for (int off = 128; off > 0; off >>= 1) {
        if (t < off) sh[t] += sh[t + off];
        __syncthreads();
    }
    if (t == 0) g_bsum[blockIdx.x] = sh[0];
}

// SB: exclusive scan of block sums — parallel Hillis-Steele (NB <= 512)
__global__ __launch_bounds__(512) void k_scan_b(int NB) {
    __shared__ int sh[512];
    int t = threadIdx.x;
    int v = (t < NB) ? g_bsum[t] : 0;
    sh[t] = v;
    __syncthreads();
    for (int off = 1; off < 512; off <<= 1) {
        int add = (t >= off) ? sh[t - off] : 0;
        __syncthreads();
        sh[t] += add;
        __syncthreads();
    }
    if (t < NB) g_bofs[t] = sh[t] - v;   // exclusive
}

// SC: in-block exclusive scan + block offset -> row_start, cursor
__global__ __launch_bounds__(256) void k_scan_c(int N) {
    __shared__ int sh[256];
    int t = threadIdx.x;
    int n = blockIdx.x * 256 + t;
    int v = (n < N) ? (g_deg[n] - 1) : 0;
    sh[t] = v;
    __syncthreads();
    for (int off = 1; off < 256; off <<= 1) {
        int add = (t >= off) ? sh[t - off] : 0;
        __syncthreads();
        sh[t] += add;
        __syncthreads();
    }
    if (n < N) {
        int excl = sh[t] - v + g_bofs[blockIdx.x];
        g_rowstart[n] = excl;
        g_cursor[n]   = excl;
    }
}

// Fill CSR: one packed 8B store per edge
__global__ void k_fill(const int* __restrict__ ei, int E) {
    int e = blockIdx.x * blockDim.x + threadIdx.x;
    if (e < E) {
        int s = ei[e];
        int d = ei[E + e];
        int pos = atomicAdd(&g_cursor[d], 1);
        g_csr[pos] = make_int2(s, __float_as_int(g_dinv[s] * g_dinv[d]));
    }
}

// ---------------------------------------------------------------------------
// GEMM1: H1[N,64] = x[N,128] @ W1[128,64]
// 128x64 block, 256 threads, 8x4 micro-tile; accumulators packed as ROW PAIRS
// in b64 regs -> 16 FFMA2 + 4 broadcast packs per k-step (fma-pipe halved).
#define KC 32
#define XT_STRIDE 132   // 128 + 4: keeps row-pair loads 8B-aligned, kills bank conflicts
__global__ __launch_bounds__(256) void k_gemm1(const float* __restrict__ x,
                                               const float* __restrict__ W,
                                               int N) {
    __shared__ float Ws[IN_F * HID_F];      // 32 KB, [k][64]
    __shared__ float xsT[KC * XT_STRIDE];   // ~16.5 KB, [k][row]
    int t  = threadIdx.x;
    int ty = t >> 4;        // 0..15 -> rows ty*8 .. ty*8+7
    int tx = t & 15;        // 0..15 -> cols tx*4 .. tx*4+3
    int row0 = blockIdx.x * 128;

    for (int i = t; i < IN_F * HID_F / 4; i += 256)
        ((float4*)Ws)[i] = ((const float4*)W)[i];

    u64 acc[4][4];   // [row-pair][col]; 0ull == (0.f, 0.f)
    #pragma unroll
    for (int p = 0; p < 4; ++p)
        #pragma unroll
        for (int c = 0; c < 4; ++c) acc[p][c] = 0ull;

    for (int kc = 0; kc < IN_F; kc += KC) {
        __syncthreads();
        // load + transpose x chunk: 128 rows x KC k-values
        for (int i = t; i < 128 * (KC / 4); i += 256) {
            int r  = i >> 3;       // row within tile
            int kq = i & 7;        // float4 index within chunk
            int row = row0 + r;
            float4 v = make_float4(0.f, 0.f, 0.f, 0.f);
            if (row < N) v = *(const float4*)&x[(size_t)row * IN_F + kc + kq * 4];
            xsT[(kq * 4 + 0) * XT_STRIDE + r] = v.x;
            xsT[(kq * 4 + 1) * XT_STRIDE + r] = v.y;
            xsT[(kq * 4 + 2) * XT_STRIDE + r] = v.z;
            xsT[(kq * 4 + 3) * XT_STRIDE + r] = v.w;
        }
        __syncthreads();
        #pragma unroll
        for (int k = 0; k < KC; ++k) {
            const float* xrow = &xsT[k * XT_STRIDE + ty * 8];
            u64 x0 = *(const u64*)&xrow[0];   // rows (0,1) of this thread's 8
            u64 x1 = *(const u64*)&xrow[2];
            u64 x2 = *(const u64*)&xrow[4];
            u64 x3 = *(const u64*)&xrow[6];
            float4 w = *(const float4*)&Ws[(kc + k) * HID_F + tx * 4];
            u64 wb0 = pack2(w.x, w.x);
            u64 wb1 = pack2(w.y, w.y);
            u64 wb2 = pack2(w.z, w.z);
            u64 wb3 = pack2(w.w, w.w);
            fma2(acc[0][0], x0, wb0); fma2(acc[0][1], x0, wb1);
            fma2(acc[0][2], x0, wb2); fma2(acc[0][3], x0, wb3);
            fma2(acc[1][0], x1, wb0); fma2(acc[1][1], x1, wb1);
            fma2(acc[1][2], x1, wb2); fma2(acc[1][3], x1, wb3);
            fma2(acc[2][0], x2, wb0); fma2(acc[2][1], x2, wb1);
            fma2(acc[2][2], x2, wb2); fma2(acc[2][3], x2, wb3);
            fma2(acc[3][0], x3, wb0); fma2(acc[3][1], x3, wb1);
            fma2(acc[3][2], x3, wb2); fma2(acc[3][3], x3, wb3);
        }
    }
    #pragma unroll
    for (int p = 0; p < 4; ++p) {
        float2 c0 = unpack2(acc[p][0]);
        float2 c1 = unpack2(acc[p][1]);
        float2 c2 = unpack2(acc[p][2]);
        float2 c3 = unpack2(acc[p][3]);
        int ra = row0 + ty * 8 + 2 * p;
        int rb = ra + 1;
        if (ra < N)
            *(float4*)&g_H1[(size_t)ra * HID_F + tx * 4] = make_float4(c0.x, c1.x, c2.x, c3.x);
        if (rb < N)
            *(float4*)&g_H1[(size_t)rb * HID_F + tx * 4] = make_float4(c0.y, c1.y, c2.y, c3.y);
    }
}

// GEMM2: H2[N,32] = agg1[N,64] @ W2[64,32]; col-pair packed accumulators
__global__ __launch_bounds__(256) void k_gemm2(const float* __restrict__ W, int N) {
    __shared__ float Ws[HID_F * OUT_F];  // 8 KB
    __shared__ float xs[32 * HID_F];     // 8 KB
    int t = threadIdx.x;
    for (int i = t; i < HID_F * OUT_F; i += 256) Ws[i] = W[i];

    int row0 = blockIdx.x * 32;
    int rows = N - row0; if (rows > 32) rows = 32;

    const float4* xg  = (const float4*)(g_agg1 + (size_t)row0 * HID_F);
    float4*       xs4 = (float4*)xs;
    const int NV = 32 * HID_F / 4;  // 512
    for (int i = t; i < NV; i += 256) {
        int r = i / (HID_F / 4);
        xs4[i] = (r < rows) ? xg[i] : make_float4(0.f, 0.f, 0.f, 0.f);
    }
    __syncthreads();

    int r = t >> 3;          // 0..31
    int g = (t & 7) * 4;     // col group: 0,4,...,28
    if (r < rows) {
        u64 a01 = 0ull, a23 = 0ull;
        #pragma unroll 16
        for (int k = 0; k < HID_F; ++k) {
            float xv = xs[r * HID_F + k];
            u64 xp  = pack2(xv, xv);
            u64 w01 = *(const u64*)&Ws[k * OUT_F + g];
            u64 w23 = *(const u64*)&Ws[k * OUT_F + g + 2];
            fma2(a01, xp, w01);
            fma2(a23, xp, w23);
        }
        float2 f01 = unpack2(a01);
        float2 f23 = unpack2(a23);
        float* out = g_H2 + (size_t)(row0 + r) * OUT_F + g;
        *(float4*)out = make_float4(f01.x, f01.y, f23.x, f23.y);
    }
}

// ---------------------------------------------------------------------------
// Gather1: one warp per node, shuffle-batched CSR; acc packed (FFMA2/edge).
__global__ __launch_bounds__(256) void k_gather1(const float* __restrict__ b1, int N) {
    int n    = (blockIdx.x * blockDim.x + threadIdx.x) >> 5;
    int lane = threadIdx.x & 31;
    if (n >= N) return;

    float dn = g_dinv[n];
    float c  = dn * dn;
    float2 h  = *(const float2*)&g_H1[(size_t)n * HID_F + lane * 2];
    float2 bb = *(const float2*)&b1[lane * 2];
    u64 acc = pack2(fmaf(h.x, c, bb.x), fmaf(h.y, c, bb.y));

    int start = g_rowstart[n];
    int end   = start + g_deg[n] - 1;
    for (int base = start; base < end; base += 32) {
        int j = base + lane;
        int   sl = 0; float wl = 0.f;
        if (j < end) { int2 p = g_csr[j]; sl = p.x; wl = __int_as_float(p.y); }
        int cnt = end - base; if (cnt > 32) cnt = 32;
        #pragma unroll 4
        for (int k = 0; k < cnt; ++k) {
            int   sk = __shfl_sync(0xffffffffu, sl, k);
            float wk = __shfl_sync(0xffffffffu, wl, k);
            u64 v = *(const u64*)&g_H1[(size_t)sk * HID_F + lane * 2];
            fma2(acc, pack2(wk, wk), v);
        }
    }
    float2 o = unpack2(acc);
    o.x = fmaxf(o.x, 0.f);
    o.y = fmaxf(o.y, 0.f);
    *(float2*)&g_agg1[(size_t)n * HID_F + lane * 2] = o;
}

// Gather2: one warp per node, 1 feature per lane, writes d_out.
__global__ __launch_bounds__(256) void k_gather2(const float* __restrict__ b2,
                                                 float* __restrict__ out, int N) {
    int n    = (blockIdx.x * blockDim.x + threadIdx.x) >> 5;
    int lane = threadIdx.x & 31;
    if (n >= N) return;

    float dn = g_dinv[n];
    float c  = dn * dn;
    float acc = fmaf(g_H2[(size_t)n * OUT_F + lane], c, b2[lane]);

    int start = g_rowstart[n];
    int end   = start + g_deg[n] - 1;
    for (int base = start; base < end; base += 32) {
        int j = base + lane;
        int   sl = 0; float wl = 0.f;
        if (j < end) { int2 p = g_csr[j]; sl = p.x; wl = __int_as_float(p.y); }
        int cnt = end - base; if (cnt > 32) cnt = 32;
        #pragma unroll 4
        for (int k = 0; k < cnt; ++k) {
            int   sk = __shfl_sync(0xffffffffu, sl, k);
            float wk = __shfl_sync(0xffffffffu, wl, k);
            acc = fmaf(wk, g_H2[(size_t)sk * OUT_F + lane], acc);
        }
    }
    out[(size_t)n * OUT_F + lane] = acc;
}

// ---------------------------------------------------------------------------
extern "C" void kernel_launch(void* const* d_in, const int* in_sizes, int n_in,
                              void* d_out, int out_size) {
    const float* x  = (const float*)d_in[0];
    const int*   ei = (const int*)d_in[1];      // int32 (JAX x64 disabled)
    const float* W1 = (const float*)d_in[2];
    const float* b1 = (const float*)d_in[3];
    const float* W2 = (const float*)d_in[4];
    const float* b2 = (const float*)d_in[5];
    float*       out = (float*)d_out;

    const int N = in_sizes[0] / IN_F;     // 100000
    const int E = in_sizes[1] / 2;        // 1600000
    const int NB = (N + 255) / 256;       // scan blocks

    const int T = 256;
    // degree + dinv; gemm1 placed 4th so the profiler snapshot lands on it
    k_deg_init <<<(N + T - 1) / T, T>>>(N);
    k_edge_prep<<<(E + T - 1) / T, T>>>(ei, E);
    k_scan_a<<<NB, 256>>>(N);                       // also computes dinv
    k_gemm1  <<<(N + 127) / 128, 256>>>(x, W1, N);  // 4th launch (profiled)
    k_scan_b<<<1, 512>>>(NB);
    k_scan_c<<<NB, 256>>>(N);
    k_fill  <<<(E + T - 1) / T, T>>>(ei, E);

    // layer 1 aggregation (relu fused)
    k_gather1<<<(N * 32 + T - 1) / T, T>>>(b1, N);

    // layer 2
    k_gemm2  <<<(N + 31) / 32, 256>>>(W2, N);
    k_gather2<<<(N * 32 + T - 1) / T, T>>>(b2, out, N);
}

// round 9
// speedup vs baseline: 1.8559x; 1.0362x over previous
#include <cuda_runtime.h>
#include <cuda_bf16.h>
#include <math.h>

// Problem constants (fixed by dataset): N=100000, E=1600000, dims 128->64->32
#define IN_F  128
#define HID_F 64
#define OUT_F 32
#define N_MAX 100000
#define E_MAX 1600000
#define NB_MAX 512         // ceil(N/256) = 391 < 512

typedef unsigned long long u64;

// ---- packed f32x2 helpers (sm_103a FFMA2 — only reachable via PTX) ----
__device__ __forceinline__ u64 pack2(float lo, float hi) {
    u64 r; asm("mov.b64 %0, {%1, %2};" : "=l"(r) : "f"(lo), "f"(hi)); return r;
}
__device__ __forceinline__ void fma2(u64& d, u64 a, u64 b) {
    asm("fma.rn.f32x2 %0, %1, %2, %0;" : "+l"(d) : "l"(a), "l"(b));
}
__device__ __forceinline__ float2 unpack2(u64 v) {
    float2 f; asm("mov.b64 {%0, %1}, %2;" : "=f"(f.x), "=f"(f.y) : "l"(v)); return f;
}

// ---- device scratch (no cudaMalloc allowed) ----
__device__ int   g_deg    [N_MAX];       // 1 + in-degree
__device__ float g_dinv   [N_MAX];
__device__ int   g_rowstart[N_MAX];      // CSR offsets (in-degree only)
__device__ int   g_cursor [N_MAX];       // fill cursors
__device__ int   g_bsum   [NB_MAX];      // per-block indegree sums
__device__ int   g_bofs   [NB_MAX];      // exclusive scan of block sums
__device__ int2  g_csr    [E_MAX];       // packed (src, w-as-int)
__device__ float g_H1  [(size_t)N_MAX * HID_F];   // x @ W1
__device__ float g_agg1[(size_t)N_MAX * HID_F];   // relu(aggregated layer-1)
__device__ float g_H2  [(size_t)N_MAX * OUT_F];   // relu_agg1 @ W2

// ---------------------------------------------------------------------------
__global__ void k_deg_init(int N) {
    int n = blockIdx.x * blockDim.x + threadIdx.x;
    if (n < N) g_deg[n] = 1;
}

__global__ void k_edge_prep(const int* __restrict__ ei, int E) {
    int e = blockIdx.x * blockDim.x + threadIdx.x;
    if (e < E) {
        int d = ei[E + e];
        atomicAdd(&g_deg[d], 1);
    }
}

// SA: per-block indegree sums + dinv
__global__ __launch_bounds__(256) void k_scan_a(int N) {
    __shared__ int sh[256];
    int t = threadIdx.x;
    int n = blockIdx.x * 256 + t;
    int deg = (n < N) ? g_deg[n] : 1;
    if (n < N) g_dinv[n] = rsqrtf((float)deg);
    sh[t] = (n < N) ? (deg - 1) : 0;
    __syncthreads();
    for (int off = 128; off > 0; off >>= 1) {
        if (t < off) sh[t] += sh[t + off];
        __syncthreads();
    }
    if (t == 0) g_bsum[blockIdx.x] = sh[0];
}

// SB: exclusive scan of block sums
__global__ __launch_bounds__(512) void k_scan_b(int NB) {
    __shared__ int sh[512];
    int t = threadIdx.x;
    int v = (t < NB) ? g_bsum[t] : 0;
    sh[t] = v;
    __syncthreads();
    for (int off = 1; off < 512; off <<= 1) {
        int add = (t >= off) ? sh[t - off] : 0;
        __syncthreads();
        sh[t] += add;
        __syncthreads();
    }
    if (t < NB) g_bofs[t] = sh[t] - v;
}

// SC: in-block exclusive scan + block offset
__global__ __launch_bounds__(256) void k_scan_c(int N) {
    __shared__ int sh[256];
    int t = threadIdx.x;
    int n = blockIdx.x * 256 + t;
    int v = (n < N) ? (g_deg[n] - 1) : 0;
    sh[t] = v;
    __syncthreads();
    for (int off = 1; off < 256; off <<= 1) {
        int add = (t >= off) ? sh[t - off] : 0;
        __syncthreads();
        sh[t] += add;
        __syncthreads();
    }
    if (n < N) {
        int excl = sh[t] - v + g_bofs[blockIdx.x];
        g_rowstart[n] = excl;
        g_cursor[n]   = excl;
    }
}

// Fill CSR: one packed 8B store per edge
__global__ void k_fill(const int* __restrict__ ei, int E) {
    int e = blockIdx.x * blockDim.x + threadIdx.x;
    if (e < E) {
        int s = ei[e];
        int d = ei[E + e];
        int pos = atomicAdd(&g_cursor[d], 1);
        g_csr[pos] = make_int2(s, __float_as_int(g_dinv[s] * g_dinv[d]));
    }
}

// ---------------------------------------------------------------------------
// GEMM1: 128x64 block, 256 threads, 8x4 micro-tile, row-pair FFMA2.
// x rows loaded as 2x LDS.128 (broadcast) + repaired into u64 (ALU movs):
// 3 LDS per thread-k instead of 5 -> shared pipe unbound.
#define KC 32
#define XT_STRIDE 132
__global__ __launch_bounds__(256) void k_gemm1(const float* __restrict__ x,
                                               const float* __restrict__ W,
                                               int N) {
    __shared__ float Ws[IN_F * HID_F];      // 32 KB, [k][64]
    __shared__ float xsT[KC * XT_STRIDE];   // ~16.5 KB, [k][row]
    int t  = threadIdx.x;
    int ty = t >> 4;
    int tx = t & 15;
    int row0 = blockIdx.x * 128;

    for (int i = t; i < IN_F * HID_F / 4; i += 256)
        ((float4*)Ws)[i] = ((const float4*)W)[i];

    u64 acc[4][4];
    #pragma unroll
    for (int p = 0; p < 4; ++p)
        #pragma unroll
        for (int c = 0; c < 4; ++c) acc[p][c] = 0ull;

    for (int kc = 0; kc < IN_F; kc += KC) {
        __syncthreads();
        for (int i = t; i < 128 * (KC / 4); i += 256) {
            int r  = i >> 3;
            int kq = i & 7;
            int row = row0 + r;
            float4 v = make_float4(0.f, 0.f, 0.f, 0.f);
            if (row < N) v = *(const float4*)&x[(size_t)row * IN_F + kc + kq * 4];
            xsT[(kq * 4 + 0) * XT_STRIDE + r] = v.x;
            xsT[(kq * 4 + 1) * XT_STRIDE + r] = v.y;
            xsT[(kq * 4 + 2) * XT_STRIDE + r] = v.z;
            xsT[(kq * 4 + 3) * XT_STRIDE + r] = v.w;
        }
        __syncthreads();
        #pragma unroll
        for (int k = 0; k < KC; ++k) {
            const float* xrow = &xsT[k * XT_STRIDE + ty * 8];
            float4 xa = *(const float4*)&xrow[0];   // LDS.128, 2-addr broadcast
            float4 xb = *(const float4*)&xrow[4];
            u64 x0 = pack2(xa.x, xa.y);
            u64 x1 = pack2(xa.z, xa.w);
            u64 x2 = pack2(xb.x, xb.y);
            u64 x3 = pack2(xb.z, xb.w);
            float4 w = *(const float4*)&Ws[(kc + k) * HID_F + tx * 4];
            u64 wb0 = pack2(w.x, w.x);
            u64 wb1 = pack2(w.y, w.y);
            u64 wb2 = pack2(w.z, w.z);
            u64 wb3 = pack2(w.w, w.w);
            fma2(acc[0][0], x0, wb0); fma2(acc[0][1], x0, wb1);
            fma2(acc[0][2], x0, wb2); fma2(acc[0][3], x0, wb3);
            fma2(acc[1][0], x1, wb0); fma2(acc[1][1], x1, wb1);
            fma2(acc[1][2], x1, wb2); fma2(acc[1][3], x1, wb3);
            fma2(acc[2][0], x2, wb0); fma2(acc[2][1], x2, wb1);
            fma2(acc[2][2], x2, wb2); fma2(acc[2][3], x2, wb3);
            fma2(acc[3][0], x3, wb0); fma2(acc[3][1], x3, wb1);
            fma2(acc[3][2], x3, wb2); fma2(acc[3][3], x3, wb3);
        }
    }
    #pragma unroll
    for (int p = 0; p < 4; ++p) {
        float2 c0 = unpack2(acc[p][0]);
        float2 c1 = unpack2(acc[p][1]);
        float2 c2 = unpack2(acc[p][2]);
        float2 c3 = unpack2(acc[p][3]);
        int ra = row0 + ty * 8 + 2 * p;
        int rb = ra + 1;
        if (ra < N)
            *(float4*)&g_H1[(size_t)ra * HID_F + tx * 4] = make_float4(c0.x, c1.x, c2.x, c3.x);
        if (rb < N)
            *(float4*)&g_H1[(size_t)rb * HID_F + tx * 4] = make_float4(c0.y, c1.y, c2.y, c3.y);
    }
}

// GEMM2: H2[N,32] = agg1[N,64] @ W2[64,32]; col-pair packed accumulators
__global__ __launch_bounds__(256) void k_gemm2(const float* __restrict__ W, int N) {
    __shared__ float Ws[HID_F * OUT_F];  // 8 KB
    __shared__ float xs[32 * HID_F];     // 8 KB
    int t = threadIdx.x;
    for (int i = t; i < HID_F * OUT_F; i += 256) Ws[i] = W[i];

    int row0 = blockIdx.x * 32;
    int rows = N - row0; if (rows > 32) rows = 32;

    const float4* xg  = (const float4*)(g_agg1 + (size_t)row0 * HID_F);
    float4*       xs4 = (float4*)xs;
    const int NV = 32 * HID_F / 4;  // 512
    for (int i = t; i < NV; i += 256) {
        int r = i / (HID_F / 4);
        xs4[i] = (r < rows) ? xg[i] : make_float4(0.f, 0.f, 0.f, 0.f);
    }
    __syncthreads();

    int r = t >> 3;
    int g = (t & 7) * 4;
    if (r < rows) {
        u64 a01 = 0ull, a23 = 0ull;
        #pragma unroll 16
        for (int k = 0; k < HID_F; ++k) {
            float xv = xs[r * HID_F + k];
            u64 xp  = pack2(xv, xv);
            u64 w01 = *(const u64*)&Ws[k * OUT_F + g];
            u64 w23 = *(const u64*)&Ws[k * OUT_F + g + 2];
            fma2(a01, xp, w01);
            fma2(a23, xp, w23);
        }
        float2 f01 = unpack2(a01);
        float2 f23 = unpack2(a23);
        float* out = g_H2 + (size_t)(row0 + r) * OUT_F + g;
        *(float4*)out = make_float4(f01.x, f01.y, f23.x, f23.y);
    }
}

// ---------------------------------------------------------------------------
// Gather1: HALF-WARP per node (2 nodes/warp). 16 lanes x float4 = 64 feats.
// Each warp-instr gather serves 2 edges (one per half) -> 2x fewer LDG instrs,
// 2x MLP. Shfl is full-warp with per-half source lanes; loop bounds are
// warp-uniform (max over halves), per-half work predicated.
__global__ __launch_bounds__(256) void k_gather1(const float* __restrict__ b1, int N) {
    int w    = (blockIdx.x * blockDim.x + threadIdx.x) >> 5;
    int lane = threadIdx.x & 31;
    int h    = lane >> 4;          // half id
    int hl   = lane & 15;          // lane within half
    int n    = 2 * w + h;
    bool active = (n < N);
    int nn = active ? n : 0;

    float dn = g_dinv[nn];
    float c  = dn * dn;
    float4 hv = *(const float4*)&g_H1[(size_t)nn * HID_F + hl * 4];
    float4 bb = *(const float4*)&b1[hl * 4];
    u64 acc0 = pack2(fmaf(hv.x, c, bb.x), fmaf(hv.y, c, bb.y));
    u64 acc1 = pack2(fmaf(hv.z, c, bb.z), fmaf(hv.w, c, bb.w));

    int start = active ? g_rowstart[nn] : 0;
    int cnt   = active ? (g_deg[nn] - 1) : 0;
    int omax  = __shfl_xor_sync(0xffffffffu, cnt, 16);
    int maxcnt = cnt > omax ? cnt : omax;        // warp-uniform

    for (int base = 0; base < maxcnt; base += 16) {
        int  sl = 0; float wl = 0.f;
        if (base + hl < cnt) {
            int2 p = g_csr[start + base + hl];
            sl = p.x; wl = __int_as_float(p.y);
        }
        int remw = maxcnt - base; if (remw > 16) remw = 16;   // warp-uniform
        int remh = cnt - base;                                 // per-half
        #pragma unroll 4
        for (int k = 0; k < remw; ++k) {
            int   sk = __shfl_sync(0xffffffffu, sl, h * 16 + k);
            float wk = __shfl_sync(0xffffffffu, wl, h * 16 + k);
            if (k < remh) {
                float4 v = *(const float4*)&g_H1[(size_t)sk * HID_F + hl * 4];
                u64 wp = pack2(wk, wk);
                fma2(acc0, wp, pack2(v.x, v.y));
                fma2(acc1, wp, pack2(v.z, v.w));
            }
        }
    }
    if (active) {
        float2 a = unpack2(acc0), b = unpack2(acc1);
        *(float4*)&g_agg1[(size_t)n * HID_F + hl * 4] =
            make_float4(fmaxf(a.x, 0.f), fmaxf(a.y, 0.f),
                        fmaxf(b.x, 0.f), fmaxf(b.y, 0.f));
    }
}

// Gather2: half-warp per node, 16 lanes x float2 = 32 feats, writes d_out.
__global__ __launch_bounds__(256) void k_gather2(const float* __restrict__ b2,
                                                 float* __restrict__ out, int N) {
    int w    = (blockIdx.x * blockDim.x + threadIdx.x) >> 5;
    int lane = threadIdx.x & 31;
    int h    = lane >> 4;
    int hl   = lane & 15;
    int n    = 2 * w + h;
    bool active = (n < N);
    int nn = active ? n : 0;

    float dn = g_dinv[nn];
    float c  = dn * dn;
    float2 hv = *(const float2*)&g_H2[(size_t)nn * OUT_F + hl * 2];
    float2 bb = *(const float2*)&b2[hl * 2];
    u64 acc = pack2(fmaf(hv.x, c, bb.x), fmaf(hv.y, c, bb.y));

    int start = active ? g_rowstart[nn] : 0;
    int cnt   = active ? (g_deg[nn] - 1) : 0;
    int omax  = __shfl_xor_sync(0xffffffffu, cnt, 16);
    int maxcnt = cnt > omax ? cnt : omax;

    for (int base = 0; base < maxcnt; base += 16) {
        int  sl = 0; float wl = 0.f;
        if (base + hl < cnt) {
            int2 p = g_csr[start + base + hl];
            sl = p.x; wl = __int_as_float(p.y);
        }
        int remw = maxcnt - base; if (remw > 16) remw = 16;
        int remh = cnt - base;
        #pragma unroll 4
        for (int k = 0; k < remw; ++k) {
            int   sk = __shfl_sync(0xffffffffu, sl, h * 16 + k);
            float wk = __shfl_sync(0xffffffffu, wl, h * 16 + k);
            if (k < remh) {
                u64 v = *(const u64*)&g_H2[(size_t)sk * OUT_F + hl * 2];
                fma2(acc, pack2(wk, wk), v);
            }
        }
    }
    if (active) {
        float2 a = unpack2(acc);
        *(float2*)&out[(size_t)n * OUT_F + hl * 2] = a;
    }
}

// ---------------------------------------------------------------------------
extern "C" void kernel_launch(void* const* d_in, const int* in_sizes, int n_in,
                              void* d_out, int out_size) {
    const float* x  = (const float*)d_in[0];
    const int*   ei = (const int*)d_in[1];      // int32 (JAX x64 disabled)
    const float* W1 = (const float*)d_in[2];
    const float* b1 = (const float*)d_in[3];
    const float* W2 = (const float*)d_in[4];
    const float* b2 = (const float*)d_in[5];
    float*       out = (float*)d_out;

    const int N = in_sizes[0] / IN_F;     // 100000
    const int E = in_sizes[1] / 2;        // 1600000
    const int NB = (N + 255) / 256;

    const int T = 256;
    k_deg_init <<<(N + T - 1) / T, T>>>(N);
    k_edge_prep<<<(E + T - 1) / T, T>>>(ei, E);
    k_scan_a<<<NB, 256>>>(N);
    k_gemm1  <<<(N + 127) / 128, 256>>>(x, W1, N);  // 4th launch (profiled)
    k_scan_b<<<1, 512>>>(NB);
    k_scan_c<<<NB, 256>>>(N);
    k_fill  <<<(E + T - 1) / T, T>>>(ei, E);

    // layer 1 aggregation (relu fused); 2 nodes per warp -> 16 nodes per block
    k_gather1<<<(N + 15) / 16, 256>>>(b1, N);

    // layer 2
    k_gemm2  <<<(N + 31) / 32, 256>>>(W2, N);
    k_gather2<<<(N + 15) / 16, 256>>>(b2, out, N);
}